// round 17
// baseline (speedup 1.0000x reference)
#include <cuda_runtime.h>
#include <math_constants.h>

#define IN_DIM   256
#define CODE_LEN 128
#define MEM_LEN  65536
#define NT       256
#define GRID     888                // 148 SMs * 6 CTAs — one resident wave
#define B_A      444                // P3 group A: mem_data copy (L2 reads)
#define NWA      (B_A * 8)          // 3552 warps in group A
#define NWB      ((GRID - B_A) * 8) // 3552 warps in group B

#define N_MD  (MEM_LEN * IN_DIM)    // 16777216 floats
#define N_MEM (MEM_LEN * CODE_LEN)  //  8388608 floats
#define N4_MD (N_MD / 4)            // 4194304 float4s
#define S_MD  ((N_MD  - 7) / 4 + 1) // 4194303 aligned slots (out+3 base)
#define S_MEM ((N_MEM - 7) / 4 + 1) // 2097151 aligned slots

// Output layout (flattened tuple, all f32):
#define OUT_MEM_OFF 1LL
#define OUT_MD_OFF  (1LL + (long long)N_MEM)
#define OUT_IDX_OFF (OUT_MD_OFF + (long long)N_MD)

// Scratch (device globals; statically armed, re-armed by the final block)
__device__ float               g_colsum[IN_DIM];                  // zero-init
__device__ float               g_colsq[IN_DIM];                   // zero-init
__device__ __align__(16) float g_enc[CODE_LEN];
__device__ int                 g_minbits = 0x7f800000;            // +inf
__device__ unsigned long long  g_argmin  = 0xFFFFFFFFFFFFFFFFULL;
__device__ unsigned            g_ticket  = 0;
__device__ unsigned            g_sdone   = 0;                     // blocks past P1
__device__ unsigned            g_encdone = 0;                     // enc rows done

#define FULL 0xFFFFFFFFu

__global__ void __launch_bounds__(NT, 6)
fused(const float* __restrict__ md_f,  float* __restrict__ out_md,
      const float* __restrict__ mem_f, float* __restrict__ out_mem,
      const int* __restrict__ idx,     float* __restrict__ out_idx,
      const float* __restrict__ x,     const float* __restrict__ W,
      const float* __restrict__ bias,  const int* __restrict__ count,
      float* __restrict__ out) {
    const float4* md4   = (const float4*)md_f;
    const float4* mem4  = (const float4*)mem_f;
    float4*       o4md  = (float4*)(out_md + 3);       // 16B-aligned
    float4*       o4mem = (float4*)(out_mem + 3);      // 16B-aligned
    const int tid  = threadIdx.x;
    const int lane = tid & 31;
    const int wid  = tid >> 5;

    __shared__ float sW[IN_DIM];
    if (blockIdx.x < CODE_LEN) sW[tid] = W[blockIdx.x * IN_DIM + tid];

    // ============ P1: stats-ONLY read of mem_data (all blocks) =============
    // Aligned float4 grid-stride; stride*4 % 256 == 0 -> fixed columns/thread.
    // Default cache policy: leaves all 64 MB resident in L2 for P3a.
    {
        const unsigned nthr = GRID * NT;               // 227328
        unsigned gtid = blockIdx.x * NT + tid;
        float s0 = 0, s1 = 0, s2 = 0, s3 = 0;
        float q0 = 0, q1 = 0, q2 = 0, q3 = 0;
        unsigned i = gtid;
        for (; i + 3u * nthr < (unsigned)N4_MD; i += 4u * nthr) {
            float4 a = md4[i];
            float4 b = md4[i + nthr];
            float4 c = md4[i + 2u * nthr];
            float4 d = md4[i + 3u * nthr];
            s0 += a.x + b.x + c.x + d.x;
            s1 += a.y + b.y + c.y + d.y;
            s2 += a.z + b.z + c.z + d.z;
            s3 += a.w + b.w + c.w + d.w;
            q0 += a.x * a.x + b.x * b.x + c.x * c.x + d.x * d.x;
            q1 += a.y * a.y + b.y * b.y + c.y * c.y + d.y * d.y;
            q2 += a.z * a.z + b.z * b.z + c.z * c.z + d.z * d.z;
            q3 += a.w * a.w + b.w * b.w + c.w * c.w + d.w * d.w;
        }
        for (; i < (unsigned)N4_MD; i += nthr) {
            float4 a = md4[i];
            s0 += a.x; q0 += a.x * a.x;
            s1 += a.y; q1 += a.y * a.y;
            s2 += a.z; q2 += a.z * a.z;
            s3 += a.w; q3 += a.w * a.w;
        }

        // Block reduce: 4 groups of 64 threads, each covers all 256 cols once.
        __shared__ float sh_s[4][IN_DIM];
        __shared__ float sh_q[4][IN_DIM];
        int col = (4 * tid) & 255, grp = tid >> 6;
        sh_s[grp][col] = s0; sh_s[grp][col + 1] = s1; sh_s[grp][col + 2] = s2; sh_s[grp][col + 3] = s3;
        sh_q[grp][col] = q0; sh_q[grp][col + 1] = q1; sh_q[grp][col + 2] = q2; sh_q[grp][col + 3] = q3;
        __syncthreads();
        float ts = sh_s[0][tid] + sh_s[1][tid] + sh_s[2][tid] + sh_s[3][tid];
        float tq = sh_q[0][tid] + sh_q[1][tid] + sh_q[2][tid] + sh_q[3][tid];
        atomicAdd(&g_colsum[tid], ts);
        atomicAdd(&g_colsq[tid],  tq);
    }

    // mem_idx copy + packed argmin (blocks 0..255 dense)
    {
        int gtid = blockIdx.x * NT + tid;
        if (gtid < MEM_LEN) {
            int v = idx[gtid];
            out_idx[gtid] = (float)v;
            unsigned long long key =
                ((unsigned long long)(unsigned)(v ^ 0x80000000) << 32) | (unsigned long long)gtid;
            #pragma unroll
            for (int off = 16; off; off >>= 1) {
                unsigned long long o = __shfl_xor_sync(FULL, key, off);
                key = (o < key) ? o : key;
            }
            if (lane == 0) atomicMin(&g_argmin, key);
        }
    }

    // Head/tail elements of both copies
    if (blockIdx.x == 0 && tid == 0) {
        out_md[0] = md_f[0]; out_md[1] = md_f[1]; out_md[2] = md_f[2];
        out_md[N_MD - 1] = md_f[N_MD - 1];
        out_mem[0] = mem_f[0]; out_mem[1] = mem_f[1]; out_mem[2] = mem_f[2];
        out_mem[N_MEM - 1] = mem_f[N_MEM - 1];
    }

    __threadfence();
    __syncthreads();
    if (tid == 0) atomicAdd(&g_sdone, 1u);

    // ============ P2: enc (blocks 0..127, gated on all stats) ==============
    if (blockIdx.x < CODE_LEN) {
        if (tid == 0) {
            while (*(volatile unsigned*)&g_sdone < (unsigned)GRID) __nanosleep(32);
        }
        __syncthreads();
        __threadfence();   // acquire all col stats
        float mean = g_colsum[tid] * (1.0f / (float)MEM_LEN);
        float var  = (g_colsq[tid] - (float)MEM_LEN * mean * mean) * (1.0f / (float)(MEM_LEN - 1));
        float sd   = sqrtf(fmaxf(var, 0.0f));
        float nv   = (sd == 0.0f) ? 0.0f : (x[tid] - mean) / sd;
        float p    = nv * sW[tid];
        #pragma unroll
        for (int off = 16; off; off >>= 1) p += __shfl_xor_sync(FULL, p, off);
        __shared__ float red[8];
        if (lane == 0) red[wid] = p;
        __syncthreads();
        if (tid == 0) {
            float a = bias[blockIdx.x];
            #pragma unroll
            for (int i = 0; i < 8; i++) a += red[i];
            g_enc[blockIdx.x] = a;
            __threadfence();
            atomicAdd(&g_encdone, 1u);
        }
    }

    // ============ P3: concurrent split =====================================
    float best = CUDART_INF_F;

    if (blockIdx.x < B_A) {
        // ---- group A: mem_data realigned copy; reads hit L2 from P1 -------
        const unsigned gw = blockIdx.x * 8u + (unsigned)wid;    // 0..3551
        const unsigned stride = NWA * 64u;                      // 227328 slots
        for (unsigned wb = gw * 64u; wb < S_MD; wb += stride) {
            unsigned k1 = wb + lane;
            unsigned k2 = k1 + 32u;
            bool ok1 = k1 < S_MD;
            bool ok2 = k2 < S_MD;
            float4 v1 = ok1 ? __ldcs(md4 + k1 + 1) : make_float4(0.f, 0.f, 0.f, 0.f);
            float4 v2 = ok2 ? __ldcs(md4 + k2 + 1) : make_float4(0.f, 0.f, 0.f, 0.f);
            float pw1 = __shfl_up_sync(FULL, v1.w, 1);
            float pw2 = __shfl_up_sync(FULL, v2.w, 1);
            if (lane == 0) {
                pw1 = md_f[4u * wb + 3u];
                if (wb + 32u < S_MD) pw2 = md_f[4u * (wb + 32u) + 3u];
            }
            if (ok1) __stcs(o4md + k1, make_float4(pw1, v1.x, v1.y, v1.z));
            if (ok2) __stcs(o4md + k2, make_float4(pw2, v2.x, v2.y, v2.z));
        }
    } else {
        // ---- group B: memory FUSED copy + L1 distance (single touch) ------
        if (tid == 0) {
            while (*(volatile unsigned*)&g_encdone < (unsigned)CODE_LEN) __nanosleep(32);
        }
        __syncthreads();
        __threadfence();   // acquire g_enc

        const float4 e = ((const float4*)g_enc)[lane];          // 4 regs/lane
        const int gwB = (blockIdx.x - B_A) * 8 + wid;           // 0..3551

        for (int r = gwB; r < MEM_LEN; r += 2 * NWB) {
            int r2 = r + NWB;
            bool ok2 = r2 < MEM_LEN;
            float4 va = __ldcs(mem4 + (unsigned)r * 32u + lane);
            float4 vb = ok2 ? __ldcs(mem4 + (unsigned)r2 * 32u + lane)
                            : make_float4(CUDART_INF_F, 0.f, 0.f, 0.f);
            // realigned copy: slot i-1 = {prev elem .w, my .xyz}
            float pa = __shfl_up_sync(FULL, va.w, 1);
            float pb = __shfl_up_sync(FULL, vb.w, 1);
            if (lane == 0) {
                if (r > 0) pa = mem_f[(unsigned)r * 128u - 1u];
                if (ok2)   pb = mem_f[(unsigned)r2 * 128u - 1u];
            }
            if (lane > 0 || r > 0)
                __stcs(o4mem + (unsigned)r * 32u + lane - 1u, make_float4(pa, va.x, va.y, va.z));
            if (ok2)
                __stcs(o4mem + (unsigned)r2 * 32u + lane - 1u, make_float4(pb, vb.x, vb.y, vb.z));
            // L1 distances
            float d1 = fabsf(va.x - e.x) + fabsf(va.y - e.y) + fabsf(va.z - e.z) + fabsf(va.w - e.w);
            float d2 = ok2 ? fabsf(vb.x - e.x) + fabsf(vb.y - e.y) + fabsf(vb.z - e.z) + fabsf(vb.w - e.w)
                           : CUDART_INF_F;
            #pragma unroll
            for (int off = 16; off; off >>= 1) {
                d1 += __shfl_xor_sync(FULL, d1, off);
                d2 += __shfl_xor_sync(FULL, d2, off);
            }
            best = fminf(best, fminf(d1, d2));
        }
    }

    // block-level min staging: ONE global atomic per block (A blocks: +inf, skip)
    {
        __shared__ float smin[8];
        if (lane == 0) smin[wid] = best;
        __syncthreads();
        if (tid == 0 && blockIdx.x >= B_A) {
            float mm = smin[0];
            #pragma unroll
            for (int j = 1; j < 8; j++) mm = fminf(mm, smin[j]);
            atomicMin(&g_minbits, __float_as_int(mm));
        }
    }

    // ============ P4: last-block final + re-arm ============================
    __threadfence();
    __syncthreads();
    __shared__ int s_last;
    if (tid == 0) s_last = (atomicAdd(&g_ticket, 1) == GRID - 1) ? 1 : 0;
    __syncthreads();
    if (s_last) {
        float loss = __int_as_float(atomicAdd(&g_minbits, 0));
        unsigned long long am = atomicAdd(&g_argmin, 0ULL);
        long long pos = (long long)(unsigned)(am & 0xFFFFFFFFULL);
        if (tid == 0) out[0] = loss;
        if (loss <= 1.0f) {
            if (tid < CODE_LEN) out[OUT_MEM_OFF + pos * CODE_LEN + tid] = g_enc[tid];
            out[OUT_MD_OFF + pos * IN_DIM + tid] = x[tid];
            if (tid == 0) out[OUT_IDX_OFF + pos] = (float)count[0];
        }
        __syncthreads();                 // done reading accumulators
        g_colsum[tid] = 0.0f;            // re-arm for next graph replay
        g_colsq[tid]  = 0.0f;
        if (tid == 0) {
            g_minbits = 0x7f800000;
            g_argmin  = 0xFFFFFFFFFFFFFFFFULL;
            g_ticket  = 0;
            g_sdone   = 0;
            g_encdone = 0;
        }
    }
}

// ---------------------------------------------------------------------------
extern "C" void kernel_launch(void* const* d_in, const int* in_sizes, int n_in,
                              void* d_out, int out_size) {
    const float* x        = (const float*)d_in[0];
    const float* memory   = (const float*)d_in[1];
    const float* mem_data = (const float*)d_in[2];
    const int*   mem_idx  = (const int*)d_in[3];
    const float* W        = (const float*)d_in[4];
    const float* b        = (const float*)d_in[5];
    const int*   count    = (const int*)d_in[6];
    float* out = (float*)d_out;

    fused<<<GRID, NT>>>(mem_data, out + OUT_MD_OFF,
                        memory,   out + OUT_MEM_OFF,
                        mem_idx,  out + OUT_IDX_OFF,
                        x, W, b, count, out);
}